// round 3
// baseline (speedup 1.0000x reference)
#include <cuda_runtime.h>
#include <cuda_bf16.h>

// Problem constants
#define B_   256
#define V_   50257
#define U_   65536
#define M_   3
#define NE_  (M_ * V_)          // 150771 CSR entries

// ---------------------------------------------------------------------------
// Scratch (static __device__ globals; allocation-free)
// ---------------------------------------------------------------------------
__device__ float    g_eT[(size_t)M_ * V_ * B_];   // exp(logits) transposed [m][j][b] (~154MB)
__device__ float    g_rowsum[M_ * B_];
__device__ float    g_escale[M_ * B_];
__device__ int      g_cnt[U_];                    // counts, then running cursors
__device__ int      g_rowptr[U_ + 1];
__device__ unsigned g_entries[NE_];               // (m<<16)|j

// ---------------------------------------------------------------------------
// 0) zero counters + rowsums
// ---------------------------------------------------------------------------
__global__ void zero_meta_kernel() {
    int i = blockIdx.x * blockDim.x + threadIdx.x;
    if (i < U_) g_cnt[i] = 0;
    if (i < M_ * B_) g_rowsum[i] = 0.f;
}

// ---------------------------------------------------------------------------
// 1) CSR count: histogram of union indices
// grid: (ceil(V/256), M), block 256
// ---------------------------------------------------------------------------
__global__ void count_kernel(const int* __restrict__ m0,
                             const int* __restrict__ m1,
                             const int* __restrict__ m2) {
    const int m = blockIdx.y;
    const int j = blockIdx.x * blockDim.x + threadIdx.x;
    if (j >= V_) return;
    const int* mp = (m == 0 ? m0 : (m == 1 ? m1 : m2));
    atomicAdd(&g_cnt[mp[j]], 1);
}

// ---------------------------------------------------------------------------
// 2) exclusive scan of 65536 counts, single block of 1024 (64 per thread)
//    writes g_rowptr and resets g_cnt to the running cursor base
// ---------------------------------------------------------------------------
__global__ void scan_kernel() {
    __shared__ int partial[1024];
    const int t = threadIdx.x;
    const int base = t * 64;

    int s = 0;
    #pragma unroll 8
    for (int i = 0; i < 64; i++) s += g_cnt[base + i];
    partial[t] = s;
    __syncthreads();

    // inclusive Hillis-Steele scan over 1024 partials
    for (int off = 1; off < 1024; off <<= 1) {
        int v = (t >= off) ? partial[t - off] : 0;
        __syncthreads();
        partial[t] += v;
        __syncthreads();
    }

    int run = (t > 0) ? partial[t - 1] : 0;
    #pragma unroll 8
    for (int i = 0; i < 64; i++) {
        int c = g_cnt[base + i];
        g_rowptr[base + i] = run;
        g_cnt[base + i] = run;      // cursor for fill
        run += c;
    }
    if (t == 1023) g_rowptr[U_] = partial[1023];
}

// ---------------------------------------------------------------------------
// 3) CSR fill
// ---------------------------------------------------------------------------
__global__ void fill_kernel(const int* __restrict__ m0,
                            const int* __restrict__ m1,
                            const int* __restrict__ m2) {
    const int m = blockIdx.y;
    const int j = blockIdx.x * blockDim.x + threadIdx.x;
    if (j >= V_) return;
    const int* mp = (m == 0 ? m0 : (m == 1 ? m1 : m2));
    const int pos = atomicAdd(&g_cnt[mp[j]], 1);
    g_entries[pos] = ((unsigned)m << 16) | (unsigned)j;
}

// ---------------------------------------------------------------------------
// 4) fused exp + rowsum + transpose:  g_eT[m][j][b] = exp(logits[m][b][j])
// grid: (JCHUNKS, B/32, M), block (32, 8). JCHUNK columns per block.
// ---------------------------------------------------------------------------
#define JCHUNK 2048
__global__ void expT_kernel(const float* __restrict__ l0,
                            const float* __restrict__ l1,
                            const float* __restrict__ l2) {
    const int m  = blockIdx.z;
    const int b0 = blockIdx.y * 32;
    const int jb = blockIdx.x * JCHUNK;
    const float* lg = (m == 0 ? l0 : (m == 1 ? l1 : l2));

    __shared__ float tile[32][33];
    const int tx = threadIdx.x;      // j lane on read, b lane on write
    const int ty = threadIdx.y;      // 0..7

    float rs[4] = {0.f, 0.f, 0.f, 0.f};

    const int jend = (jb + JCHUNK < V_) ? (jb + JCHUNK) : V_;
    for (int j0 = jb; j0 < jend; j0 += 32) {
        #pragma unroll
        for (int k = 0; k < 4; k++) {
            const int b = b0 + ty + 8 * k;
            const int j = j0 + tx;
            float e = 0.f;
            if (j < V_) e = __expf(lg[(size_t)b * V_ + j]);
            tile[ty + 8 * k][tx] = e;
            rs[k] += e;
        }
        __syncthreads();
        #pragma unroll
        for (int k = 0; k < 4; k++) {
            const int j = j0 + ty + 8 * k;
            if (j < V_)
                g_eT[((size_t)m * V_ + j) * B_ + b0 + tx] = tile[tx][ty + 8 * k];
        }
        __syncthreads();
    }

    // reduce rs across tx (warp = fixed ty)
    #pragma unroll
    for (int k = 0; k < 4; k++) {
        float v = rs[k];
        #pragma unroll
        for (int off = 16; off > 0; off >>= 1)
            v += __shfl_xor_sync(0xFFFFFFFFu, v, off);
        if (tx == 0)
            atomicAdd(&g_rowsum[m * B_ + b0 + ty + 8 * k], v);
    }
}

// ---------------------------------------------------------------------------
// 5) finalize scales:  g_escale[m*B+b] = w[m] / rowsum
// ---------------------------------------------------------------------------
__global__ void finalize_kernel(const float* __restrict__ w) {
    const int i = blockIdx.x * blockDim.x + threadIdx.x;
    if (i < M_ * B_) g_escale[i] = w[i / B_] / g_rowsum[i];
}

// ---------------------------------------------------------------------------
// 6) atomic-free gather:  out[b][u] = sum_e scale[m_e,b] * eT[m_e][j_e][b]
// grid: (U/32, B/32), block (32, 8). Warp = one u across 32 b's (coalesced).
// ---------------------------------------------------------------------------
__global__ void gather_kernel(float* __restrict__ out) {
    const int u0 = blockIdx.x * 32;
    const int b0 = blockIdx.y * 32;
    const int tx = threadIdx.x;      // b lane
    const int ty = threadIdx.y;      // u sub (0..7)

    __shared__ float tile[32][33];

    const float s0 = g_escale[0 * B_ + b0 + tx];
    const float s1 = g_escale[1 * B_ + b0 + tx];
    const float s2 = g_escale[2 * B_ + b0 + tx];

    #pragma unroll
    for (int p = 0; p < 4; p++) {
        const int u = u0 + ty + 8 * p;
        const int beg = g_rowptr[u];
        const int end = g_rowptr[u + 1];
        float acc = 0.f;
        for (int k = beg; k < end; k++) {
            const unsigned e = g_entries[k];
            const int m = (int)(e >> 16);
            const int j = (int)(e & 0xFFFFu);
            const float sc = (m == 0) ? s0 : ((m == 1) ? s1 : s2);
            acc += sc * g_eT[((size_t)m * V_ + j) * B_ + b0 + tx];
        }
        tile[tx][ty + 8 * p] = acc;
    }
    __syncthreads();

    #pragma unroll
    for (int k = 0; k < 4; k++) {
        const int b = b0 + ty + 8 * k;
        out[(size_t)b * U_ + u0 + tx] = tile[ty + 8 * k][tx];
    }
}

// ---------------------------------------------------------------------------
// kernel_launch
// inputs: logits0, logits1, logits2, map0, map1, map2, weights
// ---------------------------------------------------------------------------
extern "C" void kernel_launch(void* const* d_in, const int* in_sizes, int n_in,
                              void* d_out, int out_size) {
    const float* l0 = (const float*)d_in[0];
    const float* l1 = (const float*)d_in[1];
    const float* l2 = (const float*)d_in[2];
    const int*   m0 = (const int*)d_in[3];
    const int*   m1 = (const int*)d_in[4];
    const int*   m2 = (const int*)d_in[5];
    const float* w  = (const float*)d_in[6];
    float* out = (float*)d_out;

    // 0) zero counters / rowsums
    zero_meta_kernel<<<(U_ + 255) / 256, 256>>>();

    // 1-3) build CSR inverse map
    {
        dim3 grid((V_ + 255) / 256, M_);
        count_kernel<<<grid, 256>>>(m0, m1, m2);
        scan_kernel<<<1, 1024>>>();
        fill_kernel<<<grid, 256>>>(m0, m1, m2);
    }

    // 4) exp + rowsum + transpose
    {
        dim3 grid((V_ + JCHUNK - 1) / JCHUNK, B_ / 32, M_);
        dim3 block(32, 8);
        expT_kernel<<<grid, block>>>(l0, l1, l2);
    }

    // 5) scales
    finalize_kernel<<<(M_ * B_ + 255) / 256, 256>>>(w);

    // 6) gather (writes every output element; no zeroing pass needed)
    {
        dim3 grid(U_ / 32, B_ / 32);
        dim3 block(32, 8);
        gather_kernel<<<grid, block>>>(out);
    }
}

// round 5
// speedup vs baseline: 2.9474x; 2.9474x over previous
#include <cuda_runtime.h>
#include <cuda_bf16.h>

// Problem constants
#define B_   256
#define V_   50257
#define U_   65536
#define M_   3

// ---------------------------------------------------------------------------
// Scratch (__device__ globals; allocation-free)
// ---------------------------------------------------------------------------
__device__ float g_outT[(size_t)U_ * B_];   // batch-minor accumulator [u][b], 64MB
__device__ float g_escale[M_ * B_];         // w[m] / rowsum

// ---------------------------------------------------------------------------
// 1) zero out_T (accumulator must be zeroed every call — graph replays)
// ---------------------------------------------------------------------------
__global__ void zero_kernel(float4* __restrict__ p, int n4) {
    int i = blockIdx.x * blockDim.x + threadIdx.x;
    if (i < n4) p[i] = make_float4(0.f, 0.f, 0.f, 0.f);
}

// ---------------------------------------------------------------------------
// 2) row sums of exp(logits) -> g_escale[m*B+b] = w[m] / sum
// grid: (B, M), block 512. 4-way unrolled for MLP.
// ---------------------------------------------------------------------------
__global__ void rowsum_kernel(const float* __restrict__ l0,
                              const float* __restrict__ l1,
                              const float* __restrict__ l2,
                              const float* __restrict__ w) {
    const int b = blockIdx.x;
    const int m = blockIdx.y;
    const float* lg = (m == 0 ? l0 : (m == 1 ? l1 : l2)) + (size_t)b * V_;

    float s0 = 0.f, s1 = 0.f, s2 = 0.f, s3 = 0.f;
    int j = threadIdx.x;
    const int stride = 512;
    for (; j + 3 * stride < V_; j += 4 * stride) {
        float a = lg[j];
        float c = lg[j + stride];
        float d = lg[j + 2 * stride];
        float e = lg[j + 3 * stride];
        s0 += __expf(a);
        s1 += __expf(c);
        s2 += __expf(d);
        s3 += __expf(e);
    }
    for (; j < V_; j += stride) s0 += __expf(lg[j]);
    float s = (s0 + s1) + (s2 + s3);

    #pragma unroll
    for (int off = 16; off > 0; off >>= 1)
        s += __shfl_xor_sync(0xFFFFFFFFu, s, off);

    __shared__ float warp_sums[16];
    const int wid = threadIdx.x >> 5;
    const int lid = threadIdx.x & 31;
    if (lid == 0) warp_sums[wid] = s;
    __syncthreads();

    if (wid == 0) {
        float t = (lid < 16) ? warp_sums[lid] : 0.f;
        #pragma unroll
        for (int off = 8; off > 0; off >>= 1)
            t += __shfl_xor_sync(0xFFFFFFFFu, t, off);
        if (lid == 0) g_escale[m * B_ + b] = w[m] / t;
    }
}

// ---------------------------------------------------------------------------
// 3) vectorized scatter: out_T[u][b0..b0+3] += {s_b * exp(l[b][j])} via
//    red.global.add.v4.f32 (one 128-bit RED replaces 4 scalar atomics).
// grid: (ceil(V/256), B/16, M), block 256. Thread = one j, 16 b's (4 quads).
// ---------------------------------------------------------------------------
__global__ void scatter_kernel(const float* __restrict__ l0,
                               const float* __restrict__ l1,
                               const float* __restrict__ l2,
                               const int*   __restrict__ m0,
                               const int*   __restrict__ m1,
                               const int*   __restrict__ m2) {
    const int m = blockIdx.z;
    const int j = blockIdx.x * 256 + threadIdx.x;
    if (j >= V_) return;

    const float* lg = (m == 0 ? l0 : (m == 1 ? l1 : l2));
    const int*   mp = (m == 0 ? m0 : (m == 1 ? m1 : m2));

    const int b0 = blockIdx.y * 16;
    const int u  = mp[j];
    float* dst = g_outT + (size_t)u * B_ + b0;

    #pragma unroll
    for (int q = 0; q < 4; q++) {
        const int bb = b0 + 4 * q;
        // 4 coalesced loads (lane index = j); scales are block-uniform.
        const float e0 = __expf(lg[(size_t)(bb + 0) * V_ + j]) * g_escale[m * B_ + bb + 0];
        const float e1 = __expf(lg[(size_t)(bb + 1) * V_ + j]) * g_escale[m * B_ + bb + 1];
        const float e2 = __expf(lg[(size_t)(bb + 2) * V_ + j]) * g_escale[m * B_ + bb + 2];
        const float e3 = __expf(lg[(size_t)(bb + 3) * V_ + j]) * g_escale[m * B_ + bb + 3];
        asm volatile("red.global.add.v4.f32 [%0], {%1, %2, %3, %4};"
                     :: "l"(dst + 4 * q), "f"(e0), "f"(e1), "f"(e2), "f"(e3)
                     : "memory");
    }
}

// ---------------------------------------------------------------------------
// 4) transpose out_T[u][b] -> out[b][u], 32x32 tiles
// grid: (U/32, B/32), block (32, 8)
// ---------------------------------------------------------------------------
__global__ void transpose_kernel(float* __restrict__ out) {
    __shared__ float tile[32][33];
    const int u0 = blockIdx.x * 32;
    const int b0 = blockIdx.y * 32;
    const int tx = threadIdx.x;
    const int ty = threadIdx.y;

    #pragma unroll
    for (int k = 0; k < 4; k++) {
        const int u = u0 + ty + 8 * k;
        tile[ty + 8 * k][tx] = g_outT[(size_t)u * B_ + b0 + tx];
    }
    __syncthreads();
    #pragma unroll
    for (int k = 0; k < 4; k++) {
        const int b = b0 + ty + 8 * k;
        out[(size_t)b * U_ + u0 + tx] = tile[tx][ty + 8 * k];
    }
}

// ---------------------------------------------------------------------------
// kernel_launch
// inputs: logits0, logits1, logits2, map0, map1, map2, weights
// ---------------------------------------------------------------------------
extern "C" void kernel_launch(void* const* d_in, const int* in_sizes, int n_in,
                              void* d_out, int out_size) {
    const float* l0 = (const float*)d_in[0];
    const float* l1 = (const float*)d_in[1];
    const float* l2 = (const float*)d_in[2];
    const int*   m0 = (const int*)d_in[3];
    const int*   m1 = (const int*)d_in[4];
    const int*   m2 = (const int*)d_in[5];
    const float* w  = (const float*)d_in[6];
    float* out = (float*)d_out;

    // 1) zero accumulator (16,777,216 floats -> 4,194,304 float4)
    {
        float* p;
        cudaGetSymbolAddress((void**)&p, g_outT);
        const int n4 = (U_ * B_) / 4;
        zero_kernel<<<n4 / 256, 256>>>((float4*)p, n4);
    }

    // 2) softmax denominators -> scales
    {
        dim3 grid(B_, M_);
        rowsum_kernel<<<grid, 512>>>(l0, l1, l2, w);
    }

    // 3) vectorized scatter-add into out_T
    {
        dim3 grid((V_ + 255) / 256, B_ / 16, M_);
        scatter_kernel<<<grid, 256>>>(l0, l1, l2, m0, m1, m2);
    }

    // 4) transpose to row-major output
    {
        dim3 grid(U_ / 32, B_ / 32);
        dim3 block(32, 8);
        transpose_kernel<<<grid, block>>>(out);
    }
}